// round 2
// baseline (speedup 1.0000x reference)
#include <cuda_runtime.h>
#include <math.h>

// Problem constants
#define B    32
#define S    64
#define T    64
#define E    512
#define H    1024
#define VT   32000
#define TWOE 1024
#define FOURH 4096
#define KS   8            // K-split for per-step gates GEMM

// ---------------- scratch (device globals; no cudaMalloc allowed) ----------------
__device__ float g_enc[B * S * TWOE];            // [b][s][1024]   8 MB
__device__ float g_encmean[B * TWOE];            // [b][1024]
__device__ float g_words[B * T * E];             // row r=(t*B+b)  4 MB
__device__ float g_gatesw[(size_t)B * T * FOURH];// row r=(t*B+b)  32 MB (word part + both biases)
__device__ float g_Wcat[(size_t)FOURH * 2048];   // [n][ctx(1024) | h(1024)] 32 MB
__device__ float g_h[B * H];
__device__ float g_c[B * H];
__device__ float g_x[B * 2048];                  // [b][ctx | h]
__device__ float g_gpart[KS * B * FOURH];        // split-K partials, 4 MB
__device__ float g_hs[(size_t)B * T * H];        // [b][t][1024]   8 MB

// ---------------- prep kernels ----------------

// enc[b,s,:] = [enc_emb[src[b,s]] , pos_emb[pos[b,s]]]
__global__ void __launch_bounds__(256) k_prep_enc(const int* __restrict__ src,
                                                  const int* __restrict__ pos,
                                                  const float* __restrict__ enc_emb,
                                                  const float* __restrict__ pos_emb) {
    int bs = blockIdx.x;                 // 0..B*S-1
    int w = src[bs], p = pos[bs];
    const float4* er = (const float4*)(enc_emb + (size_t)w * E);
    const float4* pr = (const float4*)(pos_emb + (size_t)p * E);
    float4* dst = (float4*)(g_enc + (size_t)bs * TWOE);
    int t = threadIdx.x;                 // 256
    if (t < 128) dst[t] = er[t];
    else         dst[t] = pr[t - 128];
}

// words row r=(t*B+b) = dec_emb[ts[b,t]]
__global__ void __launch_bounds__(128) k_prep_words(const int* __restrict__ ts,
                                                    const float* __restrict__ dec_emb) {
    int r = blockIdx.x;                  // 0..2047
    int t = r / B, b = r % B;
    int w = ts[b * T + t];
    const float4* srcr = (const float4*)(dec_emb + (size_t)w * E);
    float4* dst = (float4*)(g_words + (size_t)r * E);
    dst[threadIdx.x] = srcr[threadIdx.x];   // 128 float4 = 512 floats
}

// W_cat[n] = [ W_ih[n, 512:1536] , W_hh[n, :] ]
__global__ void __launch_bounds__(256) k_prep_wcat(const float* __restrict__ W_ih,
                                                   const float* __restrict__ W_hh) {
    int n = blockIdx.x;                  // 0..4095
    int t = threadIdx.x;                 // 256
    const float4* a = (const float4*)(W_ih + (size_t)n * 1536 + 512);
    const float4* b = (const float4*)(W_hh + (size_t)n * 1024);
    float4* dst = (float4*)(g_Wcat + (size_t)n * 2048);
    dst[t]       = a[t];
    dst[256 + t] = b[t];
}

__global__ void __launch_bounds__(1024) k_encmean() {
    int b = blockIdx.x, d = threadIdx.x;
    float s = 0.f;
    const float* base = g_enc + (size_t)b * S * TWOE + d;
    #pragma unroll 8
    for (int i = 0; i < S; i++) s += base[(size_t)i * TWOE];
    g_encmean[b * TWOE + d] = s * (1.0f / S);
}

// h0 = encmean @ W_h0^T + b_h0 ; write to both g_h and g_c. One warp per output.
__global__ void __launch_bounds__(256) k_h0(const float* __restrict__ W_h0,
                                            const float* __restrict__ b_h0) {
    int gid = blockIdx.x * 8 + (threadIdx.x >> 5);   // warp id, 0..32767
    int lane = threadIdx.x & 31;
    int b = gid >> 10, n = gid & 1023;
    const float* a = g_encmean + b * 1024;
    const float* w = W_h0 + (size_t)n * 1024;
    float acc = 0.f;
    for (int k = lane; k < 1024; k += 32) acc += a[k] * w[k];
    #pragma unroll
    for (int o = 16; o; o >>= 1) acc += __shfl_xor_sync(0xffffffffu, acc, o);
    if (lane == 0) {
        float v = acc + b_h0[n];
        g_h[b * H + n] = v;
        g_c[b * H + n] = v;
    }
}

// ---------------- generic TN SGEMM: C[M,N] = A[M,K] * Bw[N,K]^T + bias0 (+bias1) ----------------
// 128x128 tile, KC=8, 256 threads, 8x8 microtiles. grid = (M/128, N/128).
__global__ void __launch_bounds__(256) k_sgemm128(const float* __restrict__ A, int lda,
                                                  const float* __restrict__ Bw, int ldb,
                                                  float* __restrict__ C, int ldc, int K,
                                                  const float* __restrict__ bias0,
                                                  const float* __restrict__ bias1) {
    __shared__ float As[8][132];
    __shared__ float Bs[8][132];
    int m0 = blockIdx.x * 128, n0 = blockIdx.y * 128;
    int tid = threadIdx.x;
    int tx = tid & 15, ty = tid >> 4;

    float acc[8][8];
    #pragma unroll
    for (int i = 0; i < 8; i++)
        #pragma unroll
        for (int j = 0; j < 8; j++) acc[i][j] = 0.f;

    int lrow = tid >> 1;
    int lko  = (tid & 1) * 4;
    const float* Aptr = A + (size_t)(m0 + lrow) * lda + lko;
    const float* Bptr = Bw + (size_t)(n0 + lrow) * ldb + lko;

    for (int k0 = 0; k0 < K; k0 += 8) {
        float4 av = *(const float4*)(Aptr + k0);
        float4 bv = *(const float4*)(Bptr + k0);
        __syncthreads();
        As[lko + 0][lrow] = av.x; As[lko + 1][lrow] = av.y;
        As[lko + 2][lrow] = av.z; As[lko + 3][lrow] = av.w;
        Bs[lko + 0][lrow] = bv.x; Bs[lko + 1][lrow] = bv.y;
        Bs[lko + 2][lrow] = bv.z; Bs[lko + 3][lrow] = bv.w;
        __syncthreads();
        #pragma unroll
        for (int kk = 0; kk < 8; kk++) {
            float a[8], bb[8];
            *(float4*)(a)      = *(const float4*)&As[kk][ty * 8];
            *(float4*)(a + 4)  = *(const float4*)&As[kk][ty * 8 + 4];
            *(float4*)(bb)     = *(const float4*)&Bs[kk][tx * 8];
            *(float4*)(bb + 4) = *(const float4*)&Bs[kk][tx * 8 + 4];
            #pragma unroll
            for (int i = 0; i < 8; i++)
                #pragma unroll
                for (int j = 0; j < 8; j++) acc[i][j] += a[i] * bb[j];
        }
    }
    #pragma unroll
    for (int i = 0; i < 8; i++) {
        int row = m0 + ty * 8 + i;
        float* crow = C + (size_t)row * ldc;
        #pragma unroll
        for (int j = 0; j < 8; j++) {
            int col = n0 + tx * 8 + j;
            float v = acc[i][j] + bias0[col];
            if (bias1) v += bias1[col];
            crow[col] = v;
        }
    }
}

// ---------------- per-step kernels ----------------

// attention: energy -> masked softmax -> ctx; build x = [ctx, h_prev]
__global__ void __launch_bounds__(256) k_attn(const int* __restrict__ source_lengths) {
    int b = blockIdx.x;
    __shared__ float se[64];
    __shared__ float sa[64];
    int tid = threadIdx.x, warp = tid >> 5, lane = tid & 31;
    const float* encb = g_enc + (size_t)b * S * TWOE;
    const float* hb = g_h + b * H;

    #pragma unroll
    for (int j = 0; j < 8; j++) {
        int s = warp * 8 + j;
        const float* er = encb + (size_t)s * TWOE;
        float acc = 0.f;
        for (int k = lane; k < TWOE; k += 32) acc += er[k] * hb[k];
        #pragma unroll
        for (int o = 16; o; o >>= 1) acc += __shfl_xor_sync(0xffffffffu, acc, o);
        if (lane == 0) se[s] = acc;
    }
    __syncthreads();
    if (warp == 0) {
        int len = source_lengths[b];
        float e0 = se[lane], e1 = se[lane + 32];
        float m = fmaxf(e0, e1);
        #pragma unroll
        for (int o = 16; o; o >>= 1) m = fmaxf(m, __shfl_xor_sync(0xffffffffu, m, o));
        float p0 = (lane < len)      ? expf(e0 - m) : 0.f;
        float p1 = (lane + 32 < len) ? expf(e1 - m) : 0.f;
        float ssum = p0 + p1;
        #pragma unroll
        for (int o = 16; o; o >>= 1) ssum += __shfl_xor_sync(0xffffffffu, ssum, o);
        float inv = 1.f / ssum;
        sa[lane] = p0 * inv;
        sa[lane + 32] = p1 * inv;
    }
    __syncthreads();
    // ctx: each thread 4 dims
    int d = tid * 4;
    float4 acc = make_float4(0.f, 0.f, 0.f, 0.f);
    for (int s = 0; s < S; s++) {
        float a = sa[s];
        float4 ev = *(const float4*)(encb + (size_t)s * TWOE + d);
        acc.x += a * ev.x; acc.y += a * ev.y; acc.z += a * ev.z; acc.w += a * ev.w;
    }
    *(float4*)(g_x + b * 2048 + d) = acc;
    *(float4*)(g_x + b * 2048 + 1024 + d) = *(const float4*)(hb + d);
}

// gates partial GEMM: gpart[ks][m][n] = x[m, kslice] * Wcat[n, kslice]^T
// Tile: M=32 (all), N=128, Kslice = 2048/KS = 256. 256 threads.
// mg = tid>>5 (8 groups x 4 rows = 32 rows), ng = tid&31 (32 groups x 4 cols = 128 cols).
__global__ void __launch_bounds__(256) k_gatesgemm() {
    const int KC = 32;
    __shared__ float Xs[KC][36];
    __shared__ float Ws[KC][132];
    int n0  = blockIdx.x * 128;
    int k00 = blockIdx.y * (2048 / KS);   // 256-wide slice
    int tid = threadIdx.x;
    int mg = tid >> 5;                    // 0..7 -> rows mg*4..mg*4+3
    int ng = tid & 31;                    // 0..31 -> cols ng*4..ng*4+3

    float acc[4][4];
    #pragma unroll
    for (int i = 0; i < 4; i++)
        #pragma unroll
        for (int j = 0; j < 4; j++) acc[i][j] = 0.f;

    int xr = tid >> 3;             // 0..31
    int xk = (tid & 7) << 2;       // 0,4,...,28

    for (int kc = k00; kc < k00 + (2048 / KS); kc += KC) {
        float4 xv = *(const float4*)(g_x + (size_t)xr * 2048 + kc + xk);
        float4 wv[4];
        #pragma unroll
        for (int p = 0; p < 4; p++) {
            int row = n0 + p * 32 + xr;
            wv[p] = *(const float4*)(g_Wcat + (size_t)row * 2048 + kc + xk);
        }
        __syncthreads();
        Xs[xk + 0][xr] = xv.x; Xs[xk + 1][xr] = xv.y;
        Xs[xk + 2][xr] = xv.z; Xs[xk + 3][xr] = xv.w;
        #pragma unroll
        for (int p = 0; p < 4; p++) {
            Ws[xk + 0][p * 32 + xr] = wv[p].x;
            Ws[xk + 1][p * 32 + xr] = wv[p].y;
            Ws[xk + 2][p * 32 + xr] = wv[p].z;
            Ws[xk + 3][p * 32 + xr] = wv[p].w;
        }
        __syncthreads();
        #pragma unroll 8
        for (int kk = 0; kk < KC; kk++) {
            float xa[4], wf[4];
            *(float4*)xa = *(const float4*)&Xs[kk][mg * 4];
            *(float4*)wf = *(const float4*)&Ws[kk][ng * 4];
            #pragma unroll
            for (int i = 0; i < 4; i++)
                #pragma unroll
                for (int j = 0; j < 4; j++)
                    acc[i][j] += xa[i] * wf[j];
        }
    }
    float* gp = g_gpart + (size_t)blockIdx.y * (B * FOURH);
    #pragma unroll
    for (int i = 0; i < 4; i++) {
        int m = mg * 4 + i;
        #pragma unroll
        for (int j = 0; j < 4; j++) {
            int n = n0 + ng * 4 + j;
            gp[(size_t)m * FOURH + n] = acc[i][j];
        }
    }
}

__device__ __forceinline__ float sigm(float x) { return 1.f / (1.f + expf(-x)); }

// reduce split-K partials + word gates, then LSTM pointwise. grid 128 x 256.
__global__ void __launch_bounds__(256) k_lstm(int t) {
    int idx = blockIdx.x * 256 + threadIdx.x;   // 0..32767
    int b = idx >> 10, n = idx & 1023;
    const float* gw = g_gatesw + ((size_t)t * B + b) * FOURH;
    float gi = gw[n], gf = gw[n + 1024], gg = gw[n + 2048], go = gw[n + 3072];
    #pragma unroll
    for (int s = 0; s < KS; s++) {
        const float* gp = g_gpart + (size_t)s * (B * FOURH) + (size_t)b * FOURH;
        gi += gp[n]; gf += gp[n + 1024]; gg += gp[n + 2048]; go += gp[n + 3072];
    }
    float c = g_c[idx];
    float iv = sigm(gi), fv = sigm(gf), gv = tanhf(gg), ov = sigm(go);
    c = fv * c + iv * gv;
    float h = ov * tanhf(c);
    g_c[idx] = c;
    g_h[idx] = h;
    g_hs[((size_t)b * T + t) * H + n] = h;
}

// ---------------- host ----------------
extern "C" void kernel_launch(void* const* d_in, const int* in_sizes, int n_in,
                              void* d_out, int out_size) {
    // walk inputs in metadata order, skipping size-1 scalars (max_len/target_len/force)
    int p = 0;
    auto nx = [&]() -> const void* {
        while (p < n_in && in_sizes[p] == 1) p++;
        return d_in[p++];
    };
    const int*   ts      = (const int*)nx();     // target_sentences [B,T]
    (void)nx();                                  // target_lengths (unused)
    const int*   sl      = (const int*)nx();     // source_lengths
    const int*   ss      = (const int*)nx();     // source_sentences [B,S]
    const int*   pos     = (const int*)nx();     // positions [B,S]
    const float* enc_emb = (const float*)nx();
    const float* pos_emb = (const float*)nx();
    const float* dec_emb = (const float*)nx();
    const float* W_h0    = (const float*)nx();
    const float* b_h0    = (const float*)nx();
    const float* W_ih    = (const float*)nx();
    const float* W_hh    = (const float*)nx();
    const float* b_ih    = (const float*)nx();
    const float* b_hh    = (const float*)nx();
    const float* W_out   = (const float*)nx();
    const float* b_out   = (const float*)nx();

    float *p_words, *p_gatesw, *p_hs;
    cudaGetSymbolAddress((void**)&p_words,  g_words);
    cudaGetSymbolAddress((void**)&p_gatesw, g_gatesw);
    cudaGetSymbolAddress((void**)&p_hs,     g_hs);

    // ---- prep phase ----
    k_prep_enc  <<<B * S, 256>>>(ss, pos, enc_emb, pos_emb);
    k_prep_words<<<B * T, 128>>>(ts, dec_emb);
    k_prep_wcat <<<FOURH, 256>>>(W_ih, W_hh);
    k_encmean   <<<B, 1024>>>();
    k_h0        <<<(B * H) / 8, 256>>>(W_h0, b_h0);
    // gates_w = words @ W_ih[:, :512]^T + b_ih + b_hh    (M=2048, N=4096, K=512)
    k_sgemm128<<<dim3((B * T) / 128, FOURH / 128), 256>>>(
        p_words, E, W_ih, 1536, p_gatesw, FOURH, E, b_ih, b_hh);

    // ---- sequential phase ----
    for (int t = 0; t < T; t++) {
        k_attn     <<<B, 256>>>(sl);
        k_gatesgemm<<<dim3(FOURH / 128, KS), 256>>>();
        k_lstm     <<<(B * H) / 256, 256>>>(t);
    }

    // ---- output projection: out[b*T+t, v] = hs @ W_out^T + b_out ----
    k_sgemm128<<<dim3((B * T) / 128, VT / 128), 256>>>(
        p_hs, H, W_out, H, (float*)d_out, VT, H, b_out, nullptr);
}

// round 6
// speedup vs baseline: 1.4574x; 1.4574x over previous
#include <cuda_runtime.h>
#include <cuda_bf16.h>
#include <cstdint>
#include <cstddef>
#include <math.h>

// Problem constants
#define B    32
#define S    64
#define T    64
#define E    512
#define H    1024
#define VT   32000
#define TWOE 1024
#define FOURH 4096
#define KS   8            // K-split for per-step gates GEMM

// ---------------- scratch (device globals; no cudaMalloc allowed) ----------------
__device__ float g_enc[B * S * TWOE];            // [b][s][1024]   8 MB
__device__ float g_encmean[B * TWOE];            // [b][1024]
__device__ float g_words[B * T * E];             // row r=(t*B+b)  4 MB
__device__ float g_gatesw[(size_t)B * T * FOURH];// row r=(t*B+b)  32 MB
__device__ float g_Wcat[(size_t)FOURH * 2048];   // [n][ctx(1024) | h(1024)] 32 MB
__device__ float g_h[B * H];
__device__ float g_c[B * H];
__device__ float g_x[B * 2048];                  // [b][ctx | h]
__device__ float g_gpart[KS * B * FOURH];        // split-K partials, 4 MB
// bf16 hi/lo operands for tensor-core output projection
__device__ __nv_bfloat16 g_hsHi[(size_t)B * T * H];   // row r=b*T+t
__device__ __nv_bfloat16 g_hsLo[(size_t)B * T * H];
__device__ __nv_bfloat16 g_WoHi[(size_t)VT * H];
__device__ __nv_bfloat16 g_WoLo[(size_t)VT * H];

// ---------------- warp-MMA helpers (sm_80-class: compile on base sm_103 target) ----
__device__ __forceinline__ uint32_t s2u(const void* p) {
    uint32_t a;
    asm("{ .reg .u64 t; cvta.to.shared.u64 t, %1; cvt.u32.u64 %0, t; }" : "=r"(a) : "l"(p));
    return a;
}
__device__ __forceinline__ void ldsm_x4(uint32_t* r, uint32_t addr) {
    asm volatile("ldmatrix.sync.aligned.m8n8.x4.shared.b16 {%0,%1,%2,%3}, [%4];"
                 : "=r"(r[0]), "=r"(r[1]), "=r"(r[2]), "=r"(r[3]) : "r"(addr));
}
__device__ __forceinline__ void ldsm_x2(uint32_t* r, uint32_t addr) {
    asm volatile("ldmatrix.sync.aligned.m8n8.x2.shared.b16 {%0,%1}, [%2];"
                 : "=r"(r[0]), "=r"(r[1]) : "r"(addr));
}
__device__ __forceinline__ void mma16816(float* d, const uint32_t* a, const uint32_t* b) {
    asm volatile("mma.sync.aligned.m16n8k16.row.col.f32.bf16.bf16.f32 "
                 "{%0,%1,%2,%3}, {%4,%5,%6,%7}, {%8,%9}, {%0,%1,%2,%3};"
                 : "+f"(d[0]), "+f"(d[1]), "+f"(d[2]), "+f"(d[3])
                 : "r"(a[0]), "r"(a[1]), "r"(a[2]), "r"(a[3]), "r"(b[0]), "r"(b[1]));
}
// byte offset of 16B segment (row r, seg c in 0..3) inside a 128x32 bf16 tile.
// swizzle keeps each 8-consecutive-row ldmatrix phase on 8 distinct bank groups.
__device__ __forceinline__ uint32_t swz(int r, int c) {
    return (uint32_t)(r * 64 + ((((c + (r >> 2)) & 3) ^ (r & 3)) << 4));
}

// ---------------- prep kernels ----------------

__global__ void __launch_bounds__(256) k_prep_enc(const int* __restrict__ src,
                                                  const int* __restrict__ pos,
                                                  const float* __restrict__ enc_emb,
                                                  const float* __restrict__ pos_emb) {
    int bs = blockIdx.x;
    int w = src[bs], p = pos[bs];
    const float4* er = (const float4*)(enc_emb + (size_t)w * E);
    const float4* pr = (const float4*)(pos_emb + (size_t)p * E);
    float4* dst = (float4*)(g_enc + (size_t)bs * TWOE);
    int t = threadIdx.x;
    if (t < 128) dst[t] = er[t];
    else         dst[t] = pr[t - 128];
}

__global__ void __launch_bounds__(128) k_prep_words(const int* __restrict__ ts,
                                                    const float* __restrict__ dec_emb) {
    int r = blockIdx.x;
    int t = r / B, b = r % B;
    int w = ts[b * T + t];
    const float4* srcr = (const float4*)(dec_emb + (size_t)w * E);
    float4* dst = (float4*)(g_words + (size_t)r * E);
    dst[threadIdx.x] = srcr[threadIdx.x];
}

__global__ void __launch_bounds__(256) k_prep_wcat(const float* __restrict__ W_ih,
                                                   const float* __restrict__ W_hh) {
    int n = blockIdx.x;
    int t = threadIdx.x;
    const float4* a = (const float4*)(W_ih + (size_t)n * 1536 + 512);
    const float4* b = (const float4*)(W_hh + (size_t)n * 1024);
    float4* dst = (float4*)(g_Wcat + (size_t)n * 2048);
    dst[t]       = a[t];
    dst[256 + t] = b[t];
}

__global__ void __launch_bounds__(1024) k_encmean() {
    int b = blockIdx.x, d = threadIdx.x;
    float s = 0.f;
    const float* base = g_enc + (size_t)b * S * TWOE + d;
    #pragma unroll 8
    for (int i = 0; i < S; i++) s += base[(size_t)i * TWOE];
    g_encmean[b * TWOE + d] = s * (1.0f / S);
}

__global__ void __launch_bounds__(256) k_h0(const float* __restrict__ W_h0,
                                            const float* __restrict__ b_h0) {
    int gid = blockIdx.x * 8 + (threadIdx.x >> 5);
    int lane = threadIdx.x & 31;
    int b = gid >> 10, n = gid & 1023;
    const float* a = g_encmean + b * 1024;
    const float* w = W_h0 + (size_t)n * 1024;
    float acc = 0.f;
    for (int k = lane; k < 1024; k += 32) acc += a[k] * w[k];
    #pragma unroll
    for (int o = 16; o; o >>= 1) acc += __shfl_xor_sync(0xffffffffu, acc, o);
    if (lane == 0) {
        float v = acc + b_h0[n];
        g_h[b * H + n] = v;
        g_c[b * H + n] = v;
    }
}

// convert W_out fp32 -> bf16 hi/lo
__global__ void __launch_bounds__(256) k_cvt_w(const float* __restrict__ src,
                                               __nv_bfloat16* __restrict__ hi,
                                               __nv_bfloat16* __restrict__ lo) {
    size_t i = ((size_t)blockIdx.x * 256 + threadIdx.x) * 4;
    float4 v = *(const float4*)(src + i);
    float a[4];
    a[0] = v.x; a[1] = v.y; a[2] = v.z; a[3] = v.w;
    __nv_bfloat16 h4[4], l4[4];
    #pragma unroll
    for (int j = 0; j < 4; j++) {
        __nv_bfloat16 bh = __float2bfloat16_rn(a[j]);
        h4[j] = bh;
        l4[j] = __float2bfloat16_rn(a[j] - __bfloat162float(bh));
    }
    *(uint2*)(hi + i) = *(uint2*)h4;
    *(uint2*)(lo + i) = *(uint2*)l4;
}

// ---------------- generic TN SGEMM (prep gates precompute) ----------------
__global__ void __launch_bounds__(256) k_sgemm128(const float* __restrict__ A, int lda,
                                                  const float* __restrict__ Bw, int ldb,
                                                  float* __restrict__ C, int ldc, int K,
                                                  const float* __restrict__ bias0,
                                                  const float* __restrict__ bias1) {
    __shared__ float As[8][132];
    __shared__ float Bs[8][132];
    int m0 = blockIdx.x * 128, n0 = blockIdx.y * 128;
    int tid = threadIdx.x;
    int tx = tid & 15, ty = tid >> 4;

    float acc[8][8];
    #pragma unroll
    for (int i = 0; i < 8; i++) {
        #pragma unroll
        for (int j = 0; j < 8; j++) acc[i][j] = 0.f;
    }

    int lrow = tid >> 1;
    int lko  = (tid & 1) * 4;
    const float* Aptr = A + (size_t)(m0 + lrow) * lda + lko;
    const float* Bptr = Bw + (size_t)(n0 + lrow) * ldb + lko;

    for (int k0 = 0; k0 < K; k0 += 8) {
        float4 av = *(const float4*)(Aptr + k0);
        float4 bv = *(const float4*)(Bptr + k0);
        __syncthreads();
        As[lko + 0][lrow] = av.x; As[lko + 1][lrow] = av.y;
        As[lko + 2][lrow] = av.z; As[lko + 3][lrow] = av.w;
        Bs[lko + 0][lrow] = bv.x; Bs[lko + 1][lrow] = bv.y;
        Bs[lko + 2][lrow] = bv.z; Bs[lko + 3][lrow] = bv.w;
        __syncthreads();
        #pragma unroll
        for (int kk = 0; kk < 8; kk++) {
            float a[8], bb[8];
            *(float4*)(a)      = *(const float4*)&As[kk][ty * 8];
            *(float4*)(a + 4)  = *(const float4*)&As[kk][ty * 8 + 4];
            *(float4*)(bb)     = *(const float4*)&Bs[kk][tx * 8];
            *(float4*)(bb + 4) = *(const float4*)&Bs[kk][tx * 8 + 4];
            #pragma unroll
            for (int i = 0; i < 8; i++) {
                #pragma unroll
                for (int j = 0; j < 8; j++) acc[i][j] += a[i] * bb[j];
            }
        }
    }
    #pragma unroll
    for (int i = 0; i < 8; i++) {
        int row = m0 + ty * 8 + i;
        float* crow = C + (size_t)row * ldc;
        #pragma unroll
        for (int j = 0; j < 8; j++) {
            int col = n0 + tx * 8 + j;
            float v = acc[i][j] + bias0[col];
            if (bias1) v += bias1[col];
            crow[col] = v;
        }
    }
}

// ---------------- per-step kernels ----------------

__global__ void __launch_bounds__(256) k_attn(const int* __restrict__ source_lengths) {
    int b = blockIdx.x;
    __shared__ float se[64];
    __shared__ float sa[64];
    int tid = threadIdx.x, warp = tid >> 5, lane = tid & 31;
    const float* encb = g_enc + (size_t)b * S * TWOE;
    const float* hb = g_h + b * H;

    #pragma unroll
    for (int j = 0; j < 8; j++) {
        int s = warp * 8 + j;
        const float* er = encb + (size_t)s * TWOE;
        float acc = 0.f;
        for (int k = lane; k < TWOE; k += 32) acc += er[k] * hb[k];
        #pragma unroll
        for (int o = 16; o; o >>= 1) acc += __shfl_xor_sync(0xffffffffu, acc, o);
        if (lane == 0) se[s] = acc;
    }
    __syncthreads();
    if (warp == 0) {
        int len = source_lengths[b];
        float e0 = se[lane], e1 = se[lane + 32];
        float m = fmaxf(e0, e1);
        #pragma unroll
        for (int o = 16; o; o >>= 1) m = fmaxf(m, __shfl_xor_sync(0xffffffffu, m, o));
        float p0 = (lane < len)      ? expf(e0 - m) : 0.f;
        float p1 = (lane + 32 < len) ? expf(e1 - m) : 0.f;
        float ssum = p0 + p1;
        #pragma unroll
        for (int o = 16; o; o >>= 1) ssum += __shfl_xor_sync(0xffffffffu, ssum, o);
        float inv = 1.f / ssum;
        sa[lane] = p0 * inv;
        sa[lane + 32] = p1 * inv;
    }
    __syncthreads();
    int d = tid * 4;
    float ax = 0.f, ay = 0.f, az = 0.f, aw = 0.f;
    for (int s = 0; s < S; s++) {
        float a = sa[s];
        float4 ev = *(const float4*)(encb + (size_t)s * TWOE + d);
        ax += a * ev.x; ay += a * ev.y; az += a * ev.z; aw += a * ev.w;
    }
    float* xo = g_x + b * 2048 + d;
    xo[0] = ax; xo[1] = ay; xo[2] = az; xo[3] = aw;
    float* xh = g_x + b * 2048 + 1024 + d;
    const float* hs4 = hb + d;
    xh[0] = hs4[0]; xh[1] = hs4[1]; xh[2] = hs4[2]; xh[3] = hs4[3];
}

__global__ void __launch_bounds__(256) k_gatesgemm() {
    const int KC = 32;
    __shared__ float Xs[KC][36];
    __shared__ float Ws[KC][132];
    int n0  = blockIdx.x * 128;
    int k00 = blockIdx.y * (2048 / KS);
    int tid = threadIdx.x;
    int mg = tid >> 5;
    int ng = tid & 31;

    float acc[4][4];
    #pragma unroll
    for (int i = 0; i < 4; i++) {
        #pragma unroll
        for (int j = 0; j < 4; j++) acc[i][j] = 0.f;
    }

    int xr = tid >> 3;
    int xk = (tid & 7) << 2;

    for (int kc = k00; kc < k00 + (2048 / KS); kc += KC) {
        float4 xv = *(const float4*)(g_x + (size_t)xr * 2048 + kc + xk);
        float4 wv[4];
        #pragma unroll
        for (int p = 0; p < 4; p++) {
            int row = n0 + p * 32 + xr;
            wv[p] = *(const float4*)(g_Wcat + (size_t)row * 2048 + kc + xk);
        }
        __syncthreads();
        Xs[xk + 0][xr] = xv.x; Xs[xk + 1][xr] = xv.y;
        Xs[xk + 2][xr] = xv.z; Xs[xk + 3][xr] = xv.w;
        #pragma unroll
        for (int p = 0; p < 4; p++) {
            Ws[xk + 0][p * 32 + xr] = wv[p].x;
            Ws[xk + 1][p * 32 + xr] = wv[p].y;
            Ws[xk + 2][p * 32 + xr] = wv[p].z;
            Ws[xk + 3][p * 32 + xr] = wv[p].w;
        }
        __syncthreads();
        #pragma unroll 8
        for (int kk = 0; kk < KC; kk++) {
            float xa[4], wf[4];
            *(float4*)xa = *(const float4*)&Xs[kk][mg * 4];
            *(float4*)wf = *(const float4*)&Ws[kk][ng * 4];
            #pragma unroll
            for (int i = 0; i < 4; i++) {
                #pragma unroll
                for (int j = 0; j < 4; j++)
                    acc[i][j] += xa[i] * wf[j];
            }
        }
    }
    float* gp = g_gpart + (size_t)blockIdx.y * (B * FOURH);
    #pragma unroll
    for (int i = 0; i < 4; i++) {
        int m = mg * 4 + i;
        #pragma unroll
        for (int j = 0; j < 4; j++) {
            int n = n0 + ng * 4 + j;
            gp[(size_t)m * FOURH + n] = acc[i][j];
        }
    }
}

__device__ __forceinline__ float sigm(float x) { return 1.f / (1.f + expf(-x)); }

__global__ void __launch_bounds__(256) k_lstm(int t) {
    int idx = blockIdx.x * 256 + threadIdx.x;
    int b = idx >> 10, n = idx & 1023;
    const float* gw = g_gatesw + ((size_t)t * B + b) * FOURH;
    float gi = gw[n], gf = gw[n + 1024], gg = gw[n + 2048], go = gw[n + 3072];
    #pragma unroll
    for (int s = 0; s < KS; s++) {
        const float* gp = g_gpart + (size_t)s * (B * FOURH) + (size_t)b * FOURH;
        gi += gp[n]; gf += gp[n + 1024]; gg += gp[n + 2048]; go += gp[n + 3072];
    }
    float c = g_c[idx];
    float iv = sigm(gi), fv = sigm(gf), gv = tanhf(gg), ov = sigm(go);
    c = fv * c + iv * gv;
    float h = ov * tanhf(c);
    g_c[idx] = c;
    g_h[idx] = h;
    size_t row = ((size_t)b * T + t) * H + n;
    __nv_bfloat16 hh = __float2bfloat16_rn(h);
    g_hsHi[row] = hh;
    g_hsLo[row] = __float2bfloat16_rn(h - __bfloat162float(hh));
}

// ---------------- bf16 HMMA 3-pass output projection ----------------
// C[2048,32000] = hs @ W_out^T, hi/lo split: AhiBhi + AhiBlo + AloBhi.
// CTA 128x128, 8 warps (2 M x 4 N), warp tile 64x32, BK=32, double-buffered smem.
// Stage layout: Ahi[128x32] | Alo | Bhi | Blo, each 8KB -> 32KB/stage, 64KB total.
#define PSTG 32768
#define PROJ_SMEM_BYTES (2 * PSTG)

__global__ void __launch_bounds__(256, 1) k_mmaproj(
    const __nv_bfloat16* __restrict__ Ahi, const __nv_bfloat16* __restrict__ Alo,
    const __nv_bfloat16* __restrict__ Bhi, const __nv_bfloat16* __restrict__ Blo,
    const float* __restrict__ bias, float* __restrict__ C)
{
    extern __shared__ __align__(128) char smem[];
    const uint32_t sb = s2u(smem);
    int tid = threadIdx.x, lane = tid & 31, wid = tid >> 5;
    int wm = wid & 1, wn = wid >> 1;
    int m0 = blockIdx.x * 128;    // x fastest: consecutive CTAs share the B slice in L2
    int n0 = blockIdx.y * 128;

    float acc[4][4][4];
    #pragma unroll
    for (int i = 0; i < 4; i++) {
        #pragma unroll
        for (int j = 0; j < 4; j++) {
            #pragma unroll
            for (int v = 0; v < 4; v++) acc[i][j][v] = 0.f;
        }
    }

    // loader mapping: thread -> rows (tid>>2) and (tid>>2)+64, seg tid&3
    int lr = tid >> 2;
    int lc = tid & 3;
    uint32_t so0 = swz(lr, lc);
    uint32_t so1 = swz(lr + 64, lc);
    const char* gA0h = (const char*)(Ahi + (size_t)(m0 + lr) * H + lc * 8);
    const char* gA1h = (const char*)(Ahi + (size_t)(m0 + lr + 64) * H + lc * 8);
    const char* gA0l = (const char*)(Alo + (size_t)(m0 + lr) * H + lc * 8);
    const char* gA1l = (const char*)(Alo + (size_t)(m0 + lr + 64) * H + lc * 8);
    const char* gB0h = (const char*)(Bhi + (size_t)(n0 + lr) * H + lc * 8);
    const char* gB1h = (const char*)(Bhi + (size_t)(n0 + lr + 64) * H + lc * 8);
    const char* gB0l = (const char*)(Blo + (size_t)(n0 + lr) * H + lc * 8);
    const char* gB1l = (const char*)(Blo + (size_t)(n0 + lr + 64) * H + lc * 8);

    uint4 pa0h, pa1h, pa0l, pa1l, pb0h, pb1h, pb0l, pb1l;
    #define LOADK(K0) do { size_t kb = (size_t)(K0) * 2; \
        pa0h = *(const uint4*)(gA0h + kb); pa1h = *(const uint4*)(gA1h + kb); \
        pa0l = *(const uint4*)(gA0l + kb); pa1l = *(const uint4*)(gA1l + kb); \
        pb0h = *(const uint4*)(gB0h + kb); pb1h = *(const uint4*)(gB1h + kb); \
        pb0l = *(const uint4*)(gB0l + kb); pb1l = *(const uint4*)(gB1l + kb); } while (0)
    #define STOREK(ST) do { char* s0 = smem + (ST) * PSTG; \
        *(uint4*)(s0 + so0)                = pa0h; *(uint4*)(s0 + so1)                = pa1h; \
        *(uint4*)(s0 + 8192  + so0)        = pa0l; *(uint4*)(s0 + 8192  + so1)        = pa1l; \
        *(uint4*)(s0 + 16384 + so0)        = pb0h; *(uint4*)(s0 + 16384 + so1)        = pb1h; \
        *(uint4*)(s0 + 24576 + so0)        = pb0l; *(uint4*)(s0 + 24576 + so1)        = pb1l; } while (0)

    LOADK(0);
    STOREK(0);
    __syncthreads();

    int arow = lane & 15;
    int aselh = lane >> 4;          // 0 or 1: k-seg half for x4
    int brow = lane & 7;
    int bselh = (lane >> 3) & 1;    // 0 or 1: k-seg half for x2

    for (int it = 0; it < 32; ++it) {
        if (it < 31) LOADK((it + 1) * 32);
        uint32_t stA_hi = sb + (uint32_t)(it & 1) * PSTG;
        uint32_t stA_lo = stA_hi + 8192;
        uint32_t stB_hi = stA_hi + 16384;
        uint32_t stB_lo = stA_hi + 24576;
        #pragma unroll
        for (int ks = 0; ks < 2; ++ks) {
            int c0 = ks * 2;
            uint32_t ah[4][4], al[4][4], bh[4][2], bl[4][2];
            #pragma unroll
            for (int mt = 0; mt < 4; mt++) {
                int r = wm * 64 + mt * 16 + arow;
                uint32_t off = swz(r, c0 + aselh);
                ldsm_x4(ah[mt], stA_hi + off);
                ldsm_x4(al[mt], stA_lo + off);
            }
            #pragma unroll
            for (int nt = 0; nt < 4; nt++) {
                int r = wn * 32 + nt * 8 + brow;
                uint32_t off = swz(r, c0 + bselh);
                ldsm_x2(bh[nt], stB_hi + off);
                ldsm_x2(bl[nt], stB_lo + off);
            }
            #pragma unroll
            for (int mt = 0; mt < 4; mt++) {
                #pragma unroll
                for (int nt = 0; nt < 4; nt++) {
                    mma16816(acc[mt][nt], ah[mt], bh[nt]);
                    mma16816(acc[mt][nt], ah[mt], bl[nt]);
                    mma16816(acc[mt][nt], al[mt], bh[nt]);
                }
            }
        }
        if (it < 31) STOREK((it + 1) & 1);
        __syncthreads();
    }

    // epilogue: acc mapping d0:(r=lane/4, c=(lane%3... (lane&3)*2), d1:c+1, d2:r+8, d3.
    #pragma unroll
    for (int nt = 0; nt < 4; nt++) {
        int col = n0 + wn * 32 + nt * 8 + (lane & 3) * 2;
        float b0 = bias[col], b1 = bias[col + 1];
        #pragma unroll
        for (int mt = 0; mt < 4; mt++) {
            int row = m0 + wm * 64 + mt * 16 + (lane >> 2);
            float* c0p = C + (size_t)row * VT + col;
            float* c1p = C + (size_t)(row + 8) * VT + col;
            c0p[0] = acc[mt][nt][0] + b0;
            c0p[1] = acc[mt][nt][1] + b1;
            c1p[0] = acc[mt][nt][2] + b0;
            c1p[1] = acc[mt][nt][3] + b1;
        }
    }
    #undef LOADK
    #undef STOREK
}

// ---------------- host ----------------
extern "C" void kernel_launch(void* const* d_in, const int* in_sizes, int n_in,
                              void* d_out, int out_size) {
    int p = 0;
    auto nx = [&]() -> const void* {
        while (p < n_in && in_sizes[p] == 1) p++;
        return d_in[p++];
    };
    const int*   ts      = (const int*)nx();     // target_sentences [B,T]
    (void)nx();                                  // target_lengths (unused)
    const int*   sl      = (const int*)nx();     // source_lengths
    const int*   ss      = (const int*)nx();     // source_sentences [B,S]
    const int*   pos     = (const int*)nx();     // positions [B,S]
    const float* enc_emb = (const float*)nx();
    const float* pos_emb = (const float*)nx();
    const float* dec_emb = (const float*)nx();
    const float* W_h0    = (const float*)nx();
    const float* b_h0    = (const float*)nx();
    const float* W_ih    = (const float*)nx();
    const float* W_hh    = (const float*)nx();
    const float* b_ih    = (const float*)nx();
    const float* b_hh    = (const float*)nx();
    const float* W_out   = (const float*)nx();
    const float* b_out   = (const float*)nx();

    float *p_words, *p_gatesw;
    __nv_bfloat16 *p_hsHi, *p_hsLo, *p_WoHi, *p_WoLo;
    cudaGetSymbolAddress((void**)&p_words,  g_words);
    cudaGetSymbolAddress((void**)&p_gatesw, g_gatesw);
    cudaGetSymbolAddress((void**)&p_hsHi,   g_hsHi);
    cudaGetSymbolAddress((void**)&p_hsLo,   g_hsLo);
    cudaGetSymbolAddress((void**)&p_WoHi,   g_WoHi);
    cudaGetSymbolAddress((void**)&p_WoLo,   g_WoLo);

    cudaFuncSetAttribute(k_mmaproj, cudaFuncAttributeMaxDynamicSharedMemorySize,
                         PROJ_SMEM_BYTES);

    // ---- prep phase ----
    k_prep_enc  <<<B * S, 256>>>(ss, pos, enc_emb, pos_emb);
    k_prep_words<<<B * T, 128>>>(ts, dec_emb);
    k_prep_wcat <<<FOURH, 256>>>(W_ih, W_hh);
    k_cvt_w     <<<(int)(((size_t)VT * H) / 1024), 256>>>(W_out, p_WoHi, p_WoLo);
    k_encmean   <<<B, 1024>>>();
    k_h0        <<<(B * H) / 8, 256>>>(W_h0, b_h0);
    // gates_w = words @ W_ih[:, :512]^T + b_ih + b_hh    (M=2048, N=4096, K=512)
    k_sgemm128<<<dim3((B * T) / 128, FOURH / 128), 256>>>(
        p_words, E, W_ih, 1536, p_gatesw, FOURH, E, b_ih, b_hh);

    // ---- sequential phase ----
    for (int t = 0; t < T; t++) {
        k_attn     <<<B, 256>>>(sl);
        k_gatesgemm<<<dim3(FOURH / 128, KS), 256>>>();
        k_lstm     <<<(B * H) / 256, 256>>>(t);
    }

    // ---- output projection: bf16 HMMA 3-pass ----
    k_mmaproj<<<dim3((B * T) / 128, VT / 128), 256, PROJ_SMEM_BYTES>>>(
        p_hsHi, p_hsLo, p_WoHi, p_WoLo, b_out, (float*)d_out);
}